// round 6
// baseline (speedup 1.0000x reference)
#include <cuda_runtime.h>
#include <cuda_fp16.h>
#include <cstdint>
#include <math.h>

#define BB 128
#define DD 512
#define TT 1024
#define GG 256
#define KK 32
#define HH 64
#define CC 4
#define CH 16         // CTAs per cluster == d-chunks per batch
#define DCH 32        // d rows per CTA

// Scratch (allocation-free rule: __device__ globals)
__device__ float g_u[BB*DD];
__device__ float g_c[BB*DD];
__device__ float g_R1p[BB*CH];
__device__ float g_R2p[BB*CH];
__device__ float g_A[BB*DD];

// dynamic smem layout (bytes)
#define XOFF     0            // half x[32][1024]        = 65536
#define INBOXOFF 65536        // float4 inbox[16][64]    = 16384
#define RSTDOFF  81920        // float rstd[1024]        = 4096
#define UCOFF    86016        // float2 uc[32]           = 256
#define MAXOFF   86272        // float maxb[16]          = 64
#define DENOFF   86336        // float denb[16]          = 64
#define REDOFF   86400        // float red[32]           = 128
#define SCOFF    86528        // float sSc, sScc         = 8
#define SMEM_MAIN 86784

__device__ __forceinline__ float warpSum(float v) {
    #pragma unroll
    for (int o = 16; o > 0; o >>= 1) v += __shfl_xor_sync(0xffffffffu, v, o);
    return v;
}
__device__ __forceinline__ float warpMax(float v) {
    #pragma unroll
    for (int o = 16; o > 0; o >>= 1) v = fmaxf(v, __shfl_xor_sync(0xffffffffu, v, o));
    return v;
}
__device__ __forceinline__ void stc_f4(unsigned int laddr, int rank, float4 v) {
    unsigned int ra;
    asm volatile("mapa.shared::cluster.u32 %0, %1, %2;" : "=r"(ra) : "r"(laddr), "r"(rank));
    asm volatile("st.shared::cluster.v4.f32 [%0], {%1,%2,%3,%4};"
                 :: "r"(ra), "f"(v.x), "f"(v.y), "f"(v.z), "f"(v.w) : "memory");
}
__device__ __forceinline__ void stc_f1(unsigned int laddr, int rank, float v) {
    unsigned int ra;
    asm volatile("mapa.shared::cluster.u32 %0, %1, %2;" : "=r"(ra) : "r"(laddr), "r"(rank));
    asm volatile("st.shared::cluster.f32 [%0], %1;" :: "r"(ra), "f"(v) : "memory");
}
#define CLUSTER_SYNC() do { \
    asm volatile("barrier.cluster.arrive.aligned;" ::: "memory"); \
    asm volatile("barrier.cluster.wait.aligned;" ::: "memory"); \
} while (0)

// ---------------------------------------------------------------------------
// Kernel 1: u/c precompute, chunk-parallel. grid (4, BB), 128 threads.
// Each block: KV[b,:] (redundant, cheap) then u/c for its 128 d's.
// ---------------------------------------------------------------------------
__global__ void __launch_bounds__(128) k1_prep(
        const float* __restrict__ gaf, const float* __restrict__ Wq,
        const float* __restrict__ Wkv, const float* __restrict__ Wout) {
    int chunk = blockIdx.x, b = blockIdx.y, tid = threadIdx.x;
    int w = tid >> 5, lane = tid & 31;
    __shared__ float s_gaf[GG];
    __shared__ float s_kv[KK];

    s_gaf[tid]       = gaf[b * GG + tid];
    s_gaf[tid + 128] = gaf[b * GG + tid + 128];
    __syncthreads();

    // 4 warps x 8 k's, lanes sweep g coalesced
    #pragma unroll
    for (int kk = 0; kk < 8; kk++) {
        int k = w * 8 + kk;
        float acc = 0.f;
        #pragma unroll
        for (int i = 0; i < 8; i++) {
            int g = lane + 32 * i;
            acc += s_gaf[g] * Wkv[k * GG + g];
        }
        acc = warpSum(acc);
        if (lane == 0) s_kv[k] = acc;
    }
    __syncthreads();

    int d = chunk * 128 + tid;
    float uu = 0.f;
    #pragma unroll
    for (int k = 0; k < KK; k++) uu += Wq[k * DD + d] * s_kv[k];   // coalesced
    float cc = 0.f;
    const float4* wo = (const float4*)(Wout + d * KK);
    #pragma unroll
    for (int q = 0; q < 8; q++) {
        float4 v = wo[q];
        cc += v.x * s_kv[q*4] + v.y * s_kv[q*4+1] + v.z * s_kv[q*4+2] + v.w * s_kv[q*4+3];
    }
    g_u[b * DD + d] = uu;
    g_c[b * DD + d] = cc;
}

// ---------------------------------------------------------------------------
// Fused main kernel: cluster of 16 CTAs per batch, 32 d-rows each.
// 2 CTAs/SM so barrier/phase-2 tails overlap with other clusters' streaming.
// ---------------------------------------------------------------------------
__global__ void __launch_bounds__(256, 2) __cluster_dims__(CH, 1, 1)
k_main(const float* __restrict__ tcf) {
    extern __shared__ char smem[];
    half*   x_h    = (half*)(smem + XOFF);
    float4* inbox  = (float4*)(smem + INBOXOFF);
    float*  rstd_s = (float*)(smem + RSTDOFF);
    float2* uc     = (float2*)(smem + UCOFF);
    float*  maxb   = (float*)(smem + MAXOFF);
    float*  denb   = (float*)(smem + DENOFF);
    float*  red    = (float*)(smem + REDOFF);
    float*  sSc    = (float*)(smem + SCOFF);

    const int rank = blockIdx.x;      // d-chunk index within batch
    const int b    = blockIdx.y;
    const int tid  = threadIdx.x;
    const int lane = tid & 31, w = tid >> 5;

    unsigned int smem_u32 = (unsigned int)__cvta_generic_to_shared(smem);

    if (tid < DCH) {
        int d = rank * DCH + tid;
        uc[tid] = make_float2(g_u[b * DD + d], g_c[b * DD + d]);
    }
    __syncthreads();

    // ---- Phase 1: stream own chunk (32 rows x 1024 t), fp32 stats + fp16 stash
    const float4* xp = (const float4*)(tcf + ((size_t)b * DD + (size_t)rank * DCH) * TT) + tid;
    float4 dot = {0,0,0,0}, s1 = {0,0,0,0}, s2 = {0,0,0,0}, sxc = {0,0,0,0};

    #pragma unroll 16
    for (int r = 0; r < DCH; r++) {
        float4 xv = xp[r * (TT/4)];
        float2 u_ = uc[r];
        dot.x += xv.x*u_.x; dot.y += xv.y*u_.x; dot.z += xv.z*u_.x; dot.w += xv.w*u_.x;
        s1.x  += xv.x;      s1.y  += xv.y;      s1.z  += xv.z;      s1.w  += xv.w;
        s2.x  += xv.x*xv.x; s2.y  += xv.y*xv.y; s2.z  += xv.z*xv.z; s2.w  += xv.w*xv.w;
        sxc.x += xv.x*u_.y; sxc.y += xv.y*u_.y; sxc.z += xv.z*u_.y; sxc.w += xv.w*u_.y;
        half2 h01 = __floats2half2_rn(xv.x, xv.y);
        half2 h23 = __floats2half2_rn(xv.z, xv.w);
        uint2 pk;
        pk.x = *reinterpret_cast<unsigned int*>(&h01);
        pk.y = *reinterpret_cast<unsigned int*>(&h23);
        ((uint2*)(x_h + r * TT))[tid] = pk;
    }

    // ---- Send per-t stat partials to owner CTA.
    // Thread owns t = 4*tid..4*tid+3; owner rank = tid/16; t_local = 4*(tid%16).
    {
        int dst = tid >> 4;
        unsigned int addr = smem_u32 + INBOXOFF + (unsigned int)(rank * 64 + (tid & 15) * 4) * 16;
        stc_f4(addr,      dst, make_float4(dot.x, s1.x, s2.x, sxc.x));
        stc_f4(addr + 16, dst, make_float4(dot.y, s1.y, s2.y, sxc.y));
        stc_f4(addr + 32, dst, make_float4(dot.z, s1.z, s2.z, sxc.z));
        stc_f4(addr + 48, dst, make_float4(dot.w, s1.w, s2.w, sxc.w));
    }

    // ---- In-CTA Sc/Scc (sum over all 512 d of c): tiny L2 read, overlaps sends.
    {
        float2 cv = *(const float2*)(g_c + b * DD + tid * 2);
        float ls  = cv.x + cv.y;
        float lss = cv.x * cv.x + cv.y * cv.y;
        ls = warpSum(ls); lss = warpSum(lss);
        if (lane == 0) { red[16 + w] = ls; red[24 + w] = lss; }
    }
    __syncthreads();
    if (tid == 0) {
        float a = 0.f, bb2 = 0.f;
        #pragma unroll
        for (int i = 0; i < 8; i++) { a += red[16 + i]; bb2 += red[24 + i]; }
        sSc[0] = a; sSc[1] = bb2;
    }
    CLUSTER_SYNC();

    // ---- Reduce stats for own 64 t's (threads 0..63)
    float score = 0.f, v1 = 0.f, v2 = 0.f, vx = 0.f;
    if (tid < 64) {
        float4 acc = {0,0,0,0};
        #pragma unroll
        for (int s = 0; s < CH; s++) {
            float4 v = inbox[s * 64 + tid];
            acc.x += v.x; acc.y += v.y; acc.z += v.z; acc.w += v.w;
        }
        score = acc.x * 0.17677669529663687f;   // 1/sqrt(32)
        v1 = acc.y; v2 = acc.z; vx = acc.w;
        float m = warpMax(score);
        if (lane == 0) red[w] = m;
    }
    __syncthreads();
    if (tid == 0) {
        float m = fmaxf(red[0], red[1]);
        unsigned int la = smem_u32 + MAXOFF + rank * 4;
        #pragma unroll
        for (int dst = 0; dst < CH; dst++) stc_f1(la, dst, m);
    }
    CLUSTER_SYNC();

    float M = -1e30f;
    #pragma unroll
    for (int i = 0; i < CH; i++) M = fmaxf(M, maxb[i]);
    float e = 0.f;
    if (tid < 64) {
        e = expf(score - M);
        float se = warpSum(e);
        if (lane == 0) red[w] = se;
    }
    __syncthreads();
    if (tid == 0) {
        float s = red[0] + red[1];
        unsigned int la = smem_u32 + DENOFF + rank * 4;
        #pragma unroll
        for (int dst = 0; dst < CH; dst++) stc_f1(la, dst, s);
    }
    CLUSTER_SYNC();

    float denom = 0.f;
    #pragma unroll
    for (int i = 0; i < CH; i++) denom += denb[i];
    if (tid < 64) {
        float wgt = e / denom;
        float Scb = sSc[0], Sccb = sSc[1];
        float mu = (v1 + wgt * Scb) * (1.f / DD);
        float ms = (v2 + 2.f * wgt * vx + wgt * wgt * Sccb) * (1.f / DD);
        float rs = rsqrtf(ms - mu * mu + 1e-5f);
        int tg = rank * 64 + tid;
        unsigned int la = smem_u32 + RSTDOFF + (unsigned int)tg * 4;
        #pragma unroll
        for (int dst = 0; dst < CH; dst++) stc_f1(la, dst, rs);
        float r1 = warpSum(rs * wgt);
        float r2 = warpSum(rs * mu);
        if (lane == 0) { red[w] = r1; red[8 + w] = r2; }
    }
    __syncthreads();
    if (tid == 0) {
        g_R1p[b * CH + rank] = red[0] + red[1];
        g_R2p[b * CH + rank] = red[8] + red[9];
    }
    CLUSTER_SYNC();   // all rstd values delivered everywhere

    // ---- Phase 2: A[d] = sum_t rstd[t] * x[d,t] from smem fp16 stash.
    // Warp w owns rows w*4 .. w*4+3.
    #pragma unroll
    for (int rr = 0; rr < 4; rr++) {
        int row = w * 4 + rr;
        const uint2* xr = (const uint2*)(x_h + row * TT);
        float acc = 0.f;
        #pragma unroll
        for (int j = 0; j < 8; j++) {
            int t0 = j * 128 + lane * 4;
            uint2 pk = xr[t0 >> 2];
            half2 h01 = *reinterpret_cast<half2*>(&pk.x);
            half2 h23 = *reinterpret_cast<half2*>(&pk.y);
            float2 f01 = __half22float2(h01);
            float2 f23 = __half22float2(h23);
            float4 rv = *(const float4*)(rstd_s + t0);
            acc += f01.x * rv.x + f01.y * rv.y + f23.x * rv.z + f23.y * rv.w;
        }
        acc = warpSum(acc);
        if (lane == 0) g_A[b * DD + rank * DCH + row] = acc;
    }
}

// ---------------------------------------------------------------------------
// Kernel 5: pooled + MLP head + output — warp-parallel.
// ---------------------------------------------------------------------------
__global__ void k5_head(const float* __restrict__ ln1g, const float* __restrict__ ln1b,
                        const float* __restrict__ W1, const float* __restrict__ b1,
                        const float* __restrict__ ln2g, const float* __restrict__ ln2b,
                        const float* __restrict__ W2, const float* __restrict__ b2,
                        float* __restrict__ out) {
    int b = blockIdx.x, tid = threadIdx.x;
    int w = tid >> 5, lane = tid & 31;
    __shared__ float pooled[DD];
    __shared__ float t1[HH];
    __shared__ float act[HH];
    __shared__ float smu, srstd;

    float R1 = 0.f, R2 = 0.f;
    #pragma unroll
    for (int i = 0; i < CH; i++) { R1 += g_R1p[b * CH + i]; R2 += g_R2p[b * CH + i]; }

    #pragma unroll
    for (int it = 0; it < 2; it++) {
        int d = tid + it * 256;
        pooled[d] = ln1g[d] * ((g_A[b * DD + d] + g_c[b * DD + d] * R1 - R2) * (1.f / TT)) + ln1b[d];
    }
    __syncthreads();

    // warp w computes h = 8w .. 8w+7, lanes sweep d coalesced
    #pragma unroll
    for (int hh = 0; hh < 8; hh++) {
        int h = w * 8 + hh;
        float acc = 0.f;
        #pragma unroll
        for (int i = 0; i < 16; i++) {
            int d = lane + 32 * i;
            acc += pooled[d] * W1[h * DD + d];
        }
        acc = warpSum(acc);
        if (lane == 0) t1[h] = acc + b1[h];
    }
    __syncthreads();

    if (w == 0) {
        float a = t1[lane], bb = t1[lane + 32];
        float sum = warpSum(a + bb) * (1.f / HH);
        float sq  = warpSum(a * a + bb * bb) * (1.f / HH);
        if (lane == 0) { smu = sum; srstd = rsqrtf(sq - sum * sum + 1e-5f); }
    }
    __syncthreads();

    if (tid < HH) {
        float v = (t1[tid] - smu) * srstd * ln2g[tid] + ln2b[tid];
        act[tid] = v > 0.f ? v : (expf(v) - 1.f);  // ELU
    }
    __syncthreads();

    if (w < CC) {
        float acc = act[lane] * W2[w * HH + lane] + act[lane + 32] * W2[w * HH + lane + 32];
        acc = warpSum(acc);
        if (lane == 0) out[b * CC + w] = acc + b2[w];
    }
}

extern "C" void kernel_launch(void* const* d_in, const int* in_sizes, int n_in,
                              void* d_out, int out_size) {
    const float* tcf  = (const float*)d_in[0];
    const float* gaf  = (const float*)d_in[1];
    const float* Wq   = (const float*)d_in[2];
    const float* Wkv  = (const float*)d_in[3];
    const float* Wout = (const float*)d_in[4];
    const float* ln1g = (const float*)d_in[5];
    const float* ln1b = (const float*)d_in[6];
    const float* W1   = (const float*)d_in[7];
    const float* b1   = (const float*)d_in[8];
    const float* ln2g = (const float*)d_in[9];
    const float* ln2b = (const float*)d_in[10];
    const float* W2   = (const float*)d_in[11];
    const float* b2   = (const float*)d_in[12];
    float* out = (float*)d_out;

    cudaFuncSetAttribute(k_main, cudaFuncAttributeMaxDynamicSharedMemorySize, SMEM_MAIN);
    cudaFuncSetAttribute(k_main, cudaFuncAttributeNonPortableClusterSizeAllowed, 1);

    k1_prep<<<dim3(4, BB), 128>>>(gaf, Wq, Wkv, Wout);
    k_main<<<dim3(CH, BB), 256, SMEM_MAIN>>>(tcf);
    k5_head<<<BB, 256>>>(ln1g, ln1b, W1, b1, ln2g, ln2b, W2, b2, out);
}

// round 7
// speedup vs baseline: 1.0025x; 1.0025x over previous
#include <cuda_runtime.h>
#include <cuda_fp16.h>
#include <cstdint>
#include <math.h>

#define BB 128
#define DD 512
#define TT 1024
#define GG 256
#define KK 32
#define HH 64
#define CC 4
#define CH 16         // CTAs per cluster == d-chunks per batch
#define DCH 32        // d rows per CTA

// Scratch (allocation-free rule: __device__ globals)
__device__ float g_u[BB*DD];
__device__ float g_c[BB*DD];
__device__ float g_R1p[BB*CH];
__device__ float g_R2p[BB*CH];
__device__ float g_A[BB*DD];

// dynamic smem layout (bytes)
#define XOFF     0            // half x[32][1024]        = 65536
#define INBOXOFF 65536        // float4 inbox[16][64]    = 16384
#define RSTDOFF  81920        // float rstd[1024]        = 4096
#define UCOFF    86016        // float2 uc[32]           = 256
#define MAXOFF   86272        // float maxb[16]          = 64
#define DENOFF   86336        // float denb[16]          = 64
#define REDOFF   86400        // float red[32]           = 128
#define SCOFF    86528        // float sSc, sScc         = 8
#define SMEM_MAIN 86784

__device__ __forceinline__ float warpSum(float v) {
    #pragma unroll
    for (int o = 16; o > 0; o >>= 1) v += __shfl_xor_sync(0xffffffffu, v, o);
    return v;
}
__device__ __forceinline__ float warpMax(float v) {
    #pragma unroll
    for (int o = 16; o > 0; o >>= 1) v = fmaxf(v, __shfl_xor_sync(0xffffffffu, v, o));
    return v;
}
__device__ __forceinline__ void stc_f4(unsigned int laddr, int rank, float4 v) {
    unsigned int ra;
    asm volatile("mapa.shared::cluster.u32 %0, %1, %2;" : "=r"(ra) : "r"(laddr), "r"(rank));
    asm volatile("st.shared::cluster.v4.f32 [%0], {%1,%2,%3,%4};"
                 :: "r"(ra), "f"(v.x), "f"(v.y), "f"(v.z), "f"(v.w) : "memory");
}
__device__ __forceinline__ void stc_f1(unsigned int laddr, int rank, float v) {
    unsigned int ra;
    asm volatile("mapa.shared::cluster.u32 %0, %1, %2;" : "=r"(ra) : "r"(laddr), "r"(rank));
    asm volatile("st.shared::cluster.f32 [%0], %1;" :: "r"(ra), "f"(v) : "memory");
}
#define CLUSTER_SYNC() do { \
    asm volatile("barrier.cluster.arrive.aligned;" ::: "memory"); \
    asm volatile("barrier.cluster.wait.aligned;" ::: "memory"); \
} while (0)

// ---------------------------------------------------------------------------
// Kernel 1: u/c precompute, chunk-parallel. grid (4, BB), 128 threads.
// Each block: KV[b,:] (redundant, cheap) then u/c for its 128 d's.
// ---------------------------------------------------------------------------
__global__ void __launch_bounds__(128) k1_prep(
        const float* __restrict__ gaf, const float* __restrict__ Wq,
        const float* __restrict__ Wkv, const float* __restrict__ Wout) {
    int chunk = blockIdx.x, b = blockIdx.y, tid = threadIdx.x;
    int w = tid >> 5, lane = tid & 31;
    __shared__ float s_gaf[GG];
    __shared__ float s_kv[KK];

    s_gaf[tid]       = gaf[b * GG + tid];
    s_gaf[tid + 128] = gaf[b * GG + tid + 128];
    __syncthreads();

    // 4 warps x 8 k's, lanes sweep g coalesced
    #pragma unroll
    for (int kk = 0; kk < 8; kk++) {
        int k = w * 8 + kk;
        float acc = 0.f;
        #pragma unroll
        for (int i = 0; i < 8; i++) {
            int g = lane + 32 * i;
            acc += s_gaf[g] * Wkv[k * GG + g];
        }
        acc = warpSum(acc);
        if (lane == 0) s_kv[k] = acc;
    }
    __syncthreads();

    int d = chunk * 128 + tid;
    float uu = 0.f;
    #pragma unroll
    for (int k = 0; k < KK; k++) uu += Wq[k * DD + d] * s_kv[k];   // coalesced
    float cc = 0.f;
    const float4* wo = (const float4*)(Wout + d * KK);
    #pragma unroll
    for (int q = 0; q < 8; q++) {
        float4 v = wo[q];
        cc += v.x * s_kv[q*4] + v.y * s_kv[q*4+1] + v.z * s_kv[q*4+2] + v.w * s_kv[q*4+3];
    }
    g_u[b * DD + d] = uu;
    g_c[b * DD + d] = cc;
}

// ---------------------------------------------------------------------------
// Fused main kernel: cluster of 16 CTAs per batch, 32 d-rows each.
// 2 CTAs/SM so barrier/phase-2 tails overlap with other clusters' streaming.
// ---------------------------------------------------------------------------
__global__ void __launch_bounds__(256, 2) __cluster_dims__(CH, 1, 1)
k_main(const float* __restrict__ tcf) {
    extern __shared__ char smem[];
    half*   x_h    = (half*)(smem + XOFF);
    float4* inbox  = (float4*)(smem + INBOXOFF);
    float*  rstd_s = (float*)(smem + RSTDOFF);
    float2* uc     = (float2*)(smem + UCOFF);
    float*  maxb   = (float*)(smem + MAXOFF);
    float*  denb   = (float*)(smem + DENOFF);
    float*  red    = (float*)(smem + REDOFF);
    float*  sSc    = (float*)(smem + SCOFF);

    const int rank = blockIdx.x;      // d-chunk index within batch
    const int b    = blockIdx.y;
    const int tid  = threadIdx.x;
    const int lane = tid & 31, w = tid >> 5;

    unsigned int smem_u32 = (unsigned int)__cvta_generic_to_shared(smem);

    if (tid < DCH) {
        int d = rank * DCH + tid;
        uc[tid] = make_float2(g_u[b * DD + d], g_c[b * DD + d]);
    }
    __syncthreads();

    // ---- Phase 1: stream own chunk (32 rows x 1024 t), fp32 stats + fp16 stash
    const float4* xp = (const float4*)(tcf + ((size_t)b * DD + (size_t)rank * DCH) * TT) + tid;
    float4 dot = {0,0,0,0}, s1 = {0,0,0,0}, s2 = {0,0,0,0}, sxc = {0,0,0,0};

    #pragma unroll 16
    for (int r = 0; r < DCH; r++) {
        float4 xv = xp[r * (TT/4)];
        float2 u_ = uc[r];
        dot.x += xv.x*u_.x; dot.y += xv.y*u_.x; dot.z += xv.z*u_.x; dot.w += xv.w*u_.x;
        s1.x  += xv.x;      s1.y  += xv.y;      s1.z  += xv.z;      s1.w  += xv.w;
        s2.x  += xv.x*xv.x; s2.y  += xv.y*xv.y; s2.z  += xv.z*xv.z; s2.w  += xv.w*xv.w;
        sxc.x += xv.x*u_.y; sxc.y += xv.y*u_.y; sxc.z += xv.z*u_.y; sxc.w += xv.w*u_.y;
        half2 h01 = __floats2half2_rn(xv.x, xv.y);
        half2 h23 = __floats2half2_rn(xv.z, xv.w);
        uint2 pk;
        pk.x = *reinterpret_cast<unsigned int*>(&h01);
        pk.y = *reinterpret_cast<unsigned int*>(&h23);
        ((uint2*)(x_h + r * TT))[tid] = pk;
    }

    // ---- Send per-t stat partials to owner CTA.
    // Thread owns t = 4*tid..4*tid+3; owner rank = tid/16; t_local = 4*(tid%16).
    {
        int dst = tid >> 4;
        unsigned int addr = smem_u32 + INBOXOFF + (unsigned int)(rank * 64 + (tid & 15) * 4) * 16;
        stc_f4(addr,      dst, make_float4(dot.x, s1.x, s2.x, sxc.x));
        stc_f4(addr + 16, dst, make_float4(dot.y, s1.y, s2.y, sxc.y));
        stc_f4(addr + 32, dst, make_float4(dot.z, s1.z, s2.z, sxc.z));
        stc_f4(addr + 48, dst, make_float4(dot.w, s1.w, s2.w, sxc.w));
    }

    // ---- In-CTA Sc/Scc (sum over all 512 d of c): tiny L2 read, overlaps sends.
    {
        float2 cv = *(const float2*)(g_c + b * DD + tid * 2);
        float ls  = cv.x + cv.y;
        float lss = cv.x * cv.x + cv.y * cv.y;
        ls = warpSum(ls); lss = warpSum(lss);
        if (lane == 0) { red[16 + w] = ls; red[24 + w] = lss; }
    }
    __syncthreads();
    if (tid == 0) {
        float a = 0.f, bb2 = 0.f;
        #pragma unroll
        for (int i = 0; i < 8; i++) { a += red[16 + i]; bb2 += red[24 + i]; }
        sSc[0] = a; sSc[1] = bb2;
    }
    CLUSTER_SYNC();

    // ---- Reduce stats for own 64 t's (threads 0..63)
    float score = 0.f, v1 = 0.f, v2 = 0.f, vx = 0.f;
    if (tid < 64) {
        float4 acc = {0,0,0,0};
        #pragma unroll
        for (int s = 0; s < CH; s++) {
            float4 v = inbox[s * 64 + tid];
            acc.x += v.x; acc.y += v.y; acc.z += v.z; acc.w += v.w;
        }
        score = acc.x * 0.17677669529663687f;   // 1/sqrt(32)
        v1 = acc.y; v2 = acc.z; vx = acc.w;
        float m = warpMax(score);
        if (lane == 0) red[w] = m;
    }
    __syncthreads();
    if (tid == 0) {
        float m = fmaxf(red[0], red[1]);
        unsigned int la = smem_u32 + MAXOFF + rank * 4;
        #pragma unroll
        for (int dst = 0; dst < CH; dst++) stc_f1(la, dst, m);
    }
    CLUSTER_SYNC();

    float M = -1e30f;
    #pragma unroll
    for (int i = 0; i < CH; i++) M = fmaxf(M, maxb[i]);
    float e = 0.f;
    if (tid < 64) {
        e = expf(score - M);
        float se = warpSum(e);
        if (lane == 0) red[w] = se;
    }
    __syncthreads();
    if (tid == 0) {
        float s = red[0] + red[1];
        unsigned int la = smem_u32 + DENOFF + rank * 4;
        #pragma unroll
        for (int dst = 0; dst < CH; dst++) stc_f1(la, dst, s);
    }
    CLUSTER_SYNC();

    float denom = 0.f;
    #pragma unroll
    for (int i = 0; i < CH; i++) denom += denb[i];
    if (tid < 64) {
        float wgt = e / denom;
        float Scb = sSc[0], Sccb = sSc[1];
        float mu = (v1 + wgt * Scb) * (1.f / DD);
        float ms = (v2 + 2.f * wgt * vx + wgt * wgt * Sccb) * (1.f / DD);
        float rs = rsqrtf(ms - mu * mu + 1e-5f);
        int tg = rank * 64 + tid;
        unsigned int la = smem_u32 + RSTDOFF + (unsigned int)tg * 4;
        #pragma unroll
        for (int dst = 0; dst < CH; dst++) stc_f1(la, dst, rs);
        float r1 = warpSum(rs * wgt);
        float r2 = warpSum(rs * mu);
        if (lane == 0) { red[w] = r1; red[8 + w] = r2; }
    }
    __syncthreads();
    if (tid == 0) {
        g_R1p[b * CH + rank] = red[0] + red[1];
        g_R2p[b * CH + rank] = red[8] + red[9];
    }
    CLUSTER_SYNC();   // all rstd values delivered everywhere

    // ---- Phase 2: A[d] = sum_t rstd[t] * x[d,t] from smem fp16 stash.
    // Warp w owns rows w*4 .. w*4+3.
    #pragma unroll
    for (int rr = 0; rr < 4; rr++) {
        int row = w * 4 + rr;
        const uint2* xr = (const uint2*)(x_h + row * TT);
        float acc = 0.f;
        #pragma unroll
        for (int j = 0; j < 8; j++) {
            int t0 = j * 128 + lane * 4;
            uint2 pk = xr[t0 >> 2];
            half2 h01 = *reinterpret_cast<half2*>(&pk.x);
            half2 h23 = *reinterpret_cast<half2*>(&pk.y);
            float2 f01 = __half22float2(h01);
            float2 f23 = __half22float2(h23);
            float4 rv = *(const float4*)(rstd_s + t0);
            acc += f01.x * rv.x + f01.y * rv.y + f23.x * rv.z + f23.y * rv.w;
        }
        acc = warpSum(acc);
        if (lane == 0) g_A[b * DD + rank * DCH + row] = acc;
    }
}

// ---------------------------------------------------------------------------
// Kernel 5: pooled + MLP head + output — warp-parallel.
// ---------------------------------------------------------------------------
__global__ void k5_head(const float* __restrict__ ln1g, const float* __restrict__ ln1b,
                        const float* __restrict__ W1, const float* __restrict__ b1,
                        const float* __restrict__ ln2g, const float* __restrict__ ln2b,
                        const float* __restrict__ W2, const float* __restrict__ b2,
                        float* __restrict__ out) {
    int b = blockIdx.x, tid = threadIdx.x;
    int w = tid >> 5, lane = tid & 31;
    __shared__ float pooled[DD];
    __shared__ float t1[HH];
    __shared__ float act[HH];
    __shared__ float smu, srstd;

    float R1 = 0.f, R2 = 0.f;
    #pragma unroll
    for (int i = 0; i < CH; i++) { R1 += g_R1p[b * CH + i]; R2 += g_R2p[b * CH + i]; }

    #pragma unroll
    for (int it = 0; it < 2; it++) {
        int d = tid + it * 256;
        pooled[d] = ln1g[d] * ((g_A[b * DD + d] + g_c[b * DD + d] * R1 - R2) * (1.f / TT)) + ln1b[d];
    }
    __syncthreads();

    // warp w computes h = 8w .. 8w+7, lanes sweep d coalesced
    #pragma unroll
    for (int hh = 0; hh < 8; hh++) {
        int h = w * 8 + hh;
        float acc = 0.f;
        #pragma unroll
        for (int i = 0; i < 16; i++) {
            int d = lane + 32 * i;
            acc += pooled[d] * W1[h * DD + d];
        }
        acc = warpSum(acc);
        if (lane == 0) t1[h] = acc + b1[h];
    }
    __syncthreads();

    if (w == 0) {
        float a = t1[lane], bb = t1[lane + 32];
        float sum = warpSum(a + bb) * (1.f / HH);
        float sq  = warpSum(a * a + bb * bb) * (1.f / HH);
        if (lane == 0) { smu = sum; srstd = rsqrtf(sq - sum * sum + 1e-5f); }
    }
    __syncthreads();

    if (tid < HH) {
        float v = (t1[tid] - smu) * srstd * ln2g[tid] + ln2b[tid];
        act[tid] = v > 0.f ? v : (expf(v) - 1.f);  // ELU
    }
    __syncthreads();

    if (w < CC) {
        float acc = act[lane] * W2[w * HH + lane] + act[lane + 32] * W2[w * HH + lane + 32];
        acc = warpSum(acc);
        if (lane == 0) out[b * CC + w] = acc + b2[w];
    }
}

extern "C" void kernel_launch(void* const* d_in, const int* in_sizes, int n_in,
                              void* d_out, int out_size) {
    const float* tcf  = (const float*)d_in[0];
    const float* gaf  = (const float*)d_in[1];
    const float* Wq   = (const float*)d_in[2];
    const float* Wkv  = (const float*)d_in[3];
    const float* Wout = (const float*)d_in[4];
    const float* ln1g = (const float*)d_in[5];
    const float* ln1b = (const float*)d_in[6];
    const float* W1   = (const float*)d_in[7];
    const float* b1   = (const float*)d_in[8];
    const float* ln2g = (const float*)d_in[9];
    const float* ln2b = (const float*)d_in[10];
    const float* W2   = (const float*)d_in[11];
    const float* b2   = (const float*)d_in[12];
    float* out = (float*)d_out;

    cudaFuncSetAttribute(k_main, cudaFuncAttributeMaxDynamicSharedMemorySize, SMEM_MAIN);
    cudaFuncSetAttribute(k_main, cudaFuncAttributeNonPortableClusterSizeAllowed, 1);

    k1_prep<<<dim3(4, BB), 128>>>(gaf, Wq, Wkv, Wout);
    k_main<<<dim3(CH, BB), 256, SMEM_MAIN>>>(tcf);
    k5_head<<<BB, 256>>>(ln1g, ln1b, W1, b1, ln2g, ln2b, W2, b2, out);
}